// round 12
// baseline (speedup 1.0000x reference)
#include <cuda_runtime.h>
#include <cuda_fp16.h>
#include <cstdint>

#define Bn 4
#define Tn 1024
#define Sn 1024
#define Hn 16
#define Dn 64
#define RS (Hn*Dn)
#define MQc 128              // queries per CTA
#define NKC 64               // keys per chunk
#define NCH (Sn/NKC)         // 16
#define NT 128

// per-(b,h,chunk) scratch: [K fp16 8KB][V fp16 8KB], swizzled smem-image layout
#define CH_B 16384
#define OFF_K 0
#define OFF_V 8192
__device__ __align__(128) unsigned char g_kv[(size_t)Bn*Hn*NCH*CH_B];   // 16 MB

// smem: K double buffer 0/8K, V double buffer 16K/24K
#define SM_V 16384
#define SMEM_MAIN 32768

// exp(x) = ex2(x * log2e); fold log2e/8 into Q scale
#define QSCALE 0.18033688011112042f

// ---------------- PTX wrappers ----------------
__device__ __forceinline__ uint32_t smem_u32(const void* p) {
    uint32_t a;
    asm("{ .reg .u64 t; cvta.to.shared.u64 t, %1; cvt.u32.u64 %0, t; }" : "=r"(a) : "l"(p));
    return a;
}
__device__ __forceinline__ void ldsm_x4(uint32_t* r, uint32_t addr) {
    asm volatile("ldmatrix.sync.aligned.m8n8.x4.shared.b16 {%0,%1,%2,%3}, [%4];"
        : "=r"(r[0]), "=r"(r[1]), "=r"(r[2]), "=r"(r[3]) : "r"(addr));
}
__device__ __forceinline__ void ldsm_x4_t(uint32_t* r, uint32_t addr) {
    asm volatile("ldmatrix.sync.aligned.m8n8.x4.trans.shared.b16 {%0,%1,%2,%3}, [%4];"
        : "=r"(r[0]), "=r"(r[1]), "=r"(r[2]), "=r"(r[3]) : "r"(addr));
}
__device__ __forceinline__ void mma_f16(float* c, const uint32_t* a, uint32_t b0, uint32_t b1) {
    asm volatile("mma.sync.aligned.m16n8k16.row.col.f32.f16.f16.f32 "
        "{%0,%1,%2,%3}, {%4,%5,%6,%7}, {%8,%9}, {%0,%1,%2,%3};"
        : "+f"(c[0]), "+f"(c[1]), "+f"(c[2]), "+f"(c[3])
        : "r"(a[0]), "r"(a[1]), "r"(a[2]), "r"(a[3]), "r"(b0), "r"(b1));
}
__device__ __forceinline__ void cpa16(uint32_t s, const void* g) {
    asm volatile("cp.async.cg.shared.global [%0], [%1], 16;" :: "r"(s), "l"(g));
}
#define CP_COMMIT() asm volatile("cp.async.commit_group;" ::: "memory")
template<int N> __device__ __forceinline__ void cp_wait() {
    asm volatile("cp.async.wait_group %0;" :: "n"(N) : "memory");
}
__device__ __forceinline__ uint32_t packh2(float a, float b) {
    __half2 h = __floats2half2_rn(a, b);
    return *(uint32_t*)&h;
}
__device__ __forceinline__ float ex2f(float x) {
    float r;
    asm("ex2.approx.f32 %0, %1;" : "=f"(r) : "f"(x));
    return r;
}

// =================== prep: fp32 K/V -> fp16 swizzled 64-key tiles ===================
__global__ __launch_bounds__(128)
void prep_kernel(const float* __restrict__ k, const float* __restrict__ v) {
    const int c = blockIdx.x, h = blockIdx.y, b = blockIdx.z, tid = threadIdx.x;
    const float* kb = k + (((size_t)b * Sn + c * NKC) * Hn + h) * Dn;
    const float* vb = v + (((size_t)b * Sn + c * NKC) * Hn + h) * Dn;
    unsigned char* dst = g_kv + (size_t)((b * Hn + h) * NCH + c) * CH_B;
    #pragma unroll
    for (int u = 0; u < 8; u++) {
        int fid = tid + u * 128;
        int r = fid >> 4, c4 = fid & 15;
        uint32_t so = (uint32_t)(r * 128 + c4 * 8) ^ ((uint32_t)(r & 7) << 4);
        float4 x = *(const float4*)(kb + (size_t)r * RS + c4 * 4);
        *(uint2*)(dst + OFF_K + so) = make_uint2(packh2(x.x, x.y), packh2(x.z, x.w));
        float4 y = *(const float4*)(vb + (size_t)r * RS + c4 * 4);
        *(uint2*)(dst + OFF_V + so) = make_uint2(packh2(y.x, y.y), packh2(y.z, y.w));
    }
}

// =================== main attention kernel ===================
__global__ __launch_bounds__(NT, 4)
void attn_main(const float* __restrict__ q,
               float* __restrict__ out_attn, float* __restrict__ out_probs) {
    extern __shared__ char sm[];
    const uint32_t smb = smem_u32(sm);
    const int tid = threadIdx.x, lane = tid & 31, w = tid >> 5;
    const int band = w * 32;                  // warp owns 32 query rows
    const int t0 = blockIdx.x * MQc, h = blockIdx.y, b = blockIdx.z;
    const int g = lane >> 2, t = lane & 3;

    const unsigned char* kvb = g_kv + (size_t)((b * Hn + h) * NCH) * CH_B;
    const float* qbase = q + (((size_t)b * Tn + t0 + band + g) * Hn + h) * Dn;

    // ---- Q fp16 fragments, 2 m-tiles, scale (log2e/8) folded in ----
    uint32_t qf[2][4][4];
    #pragma unroll
    for (int m = 0; m < 2; m++) {
        const float* qrG = qbase + (size_t)(m * 16) * RS;
        const float* qrH = qrG + 8 * RS;
        #pragma unroll
        for (int ks = 0; ks < 4; ks++) {
            float2 f0 = *(const float2*)(qrG + ks * 16 + 2 * t);
            float2 f1 = *(const float2*)(qrH + ks * 16 + 2 * t);
            float2 f2 = *(const float2*)(qrG + ks * 16 + 2 * t + 8);
            float2 f3 = *(const float2*)(qrH + ks * 16 + 2 * t + 8);
            qf[m][ks][0] = packh2(f0.x * QSCALE, f0.y * QSCALE);
            qf[m][ks][1] = packh2(f1.x * QSCALE, f1.y * QSCALE);
            qf[m][ks][2] = packh2(f2.x * QSCALE, f2.y * QSCALE);
            qf[m][ks][3] = packh2(f3.x * QSCALE, f3.y * QSCALE);
        }
    }

    // ldmatrix lane addressing (within-tile SW128)
    const uint32_t rowoff = ((lane >> 4) & 1) * 8 + (lane & 7);
    const uint32_t colsel = ((lane >> 3) & 1) * 16;
    const uint32_t lbase = rowoff * 128 + colsel;
    const uint32_t lxor = (rowoff & 7) << 4;

    float sG[2] = {0.f, 0.f}, sH[2] = {0.f, 0.f};

    // ================= Pass A: rowsums (double-buffered 8KB K tiles, 16-key slabs) =================
    {
        #pragma unroll
        for (int u = 0; u < 4; u++)
            cpa16(smb + tid * 16 + u * 2048, kvb + OFF_K + tid * 16 + u * 2048);
        CP_COMMIT();
        #pragma unroll
        for (int u = 0; u < 4; u++)
            cpa16(smb + 8192 + tid * 16 + u * 2048, kvb + CH_B + OFF_K + tid * 16 + u * 2048);
        CP_COMMIT();

        for (int c = 0; c < NCH; c++) {
            cp_wait<1>();
            __syncthreads();
            const uint32_t kb_s = smb + (uint32_t)(c & 1) * 8192;

            #pragma unroll
            for (int jj = 0; jj < 4; jj++) {
                float S[2][2][4];
                #pragma unroll
                for (int m = 0; m < 2; m++)
                    #pragma unroll
                    for (int i = 0; i < 2; i++)
                        { S[m][i][0] = 0.f; S[m][i][1] = 0.f; S[m][i][2] = 0.f; S[m][i][3] = 0.f; }
                #pragma unroll
                for (int ks = 0; ks < 4; ks++) {
                    uint32_t bh[4];
                    ldsm_x4(bh, (kb_s + jj * 2048 + ks * 32 + lbase) ^ lxor);
                    mma_f16(S[0][0], qf[0][ks], bh[0], bh[1]);
                    mma_f16(S[0][1], qf[0][ks], bh[2], bh[3]);
                    mma_f16(S[1][0], qf[1][ks], bh[0], bh[1]);
                    mma_f16(S[1][1], qf[1][ks], bh[2], bh[3]);
                }
                #pragma unroll
                for (int m = 0; m < 2; m++)
                    #pragma unroll
                    for (int i = 0; i < 2; i++) {
                        sG[m] += ex2f(S[m][i][0]) + ex2f(S[m][i][1]);
                        sH[m] += ex2f(S[m][i][2]) + ex2f(S[m][i][3]);
                    }
            }
            __syncthreads();
            if (c + 2 < NCH) {
                const unsigned char* src = kvb + (size_t)(c + 2) * CH_B + OFF_K;
                uint32_t d = smb + (uint32_t)(c & 1) * 8192;
                #pragma unroll
                for (int u = 0; u < 4; u++)
                    cpa16(d + tid * 16 + u * 2048, src + tid * 16 + u * 2048);
            }
            CP_COMMIT();
        }
        cp_wait<0>();
        __syncthreads();
    }
    #pragma unroll
    for (int m = 0; m < 2; m++) {
        sG[m] += __shfl_xor_sync(0xffffffffu, sG[m], 1);
        sG[m] += __shfl_xor_sync(0xffffffffu, sG[m], 2);
        sH[m] += __shfl_xor_sync(0xffffffffu, sH[m], 1);
        sH[m] += __shfl_xor_sync(0xffffffffu, sH[m], 2);
    }
    const float iG0 = 1.f / sG[0], iH0 = 1.f / sH[0];
    const float iG1 = 1.f / sG[1], iH1 = 1.f / sH[1];

    // pass B prologue: K0 + V0 in one group
    #pragma unroll
    for (int u = 0; u < 4; u++)
        cpa16(smb + tid * 16 + u * 2048, kvb + OFF_K + tid * 16 + u * 2048);
    #pragma unroll
    for (int u = 0; u < 4; u++)
        cpa16(smb + SM_V + tid * 16 + u * 2048, kvb + OFF_V + tid * 16 + u * 2048);
    CP_COMMIT();

    // ================= Pass B: probs + PV (16-key groups, normalized P) =================
    float O[2][8][4];
    #pragma unroll
    for (int m = 0; m < 2; m++)
        #pragma unroll
        for (int i = 0; i < 8; i++)
            { O[m][i][0] = 0.f; O[m][i][1] = 0.f; O[m][i][2] = 0.f; O[m][i][3] = 0.f; }

    float* prow0G = out_probs + (((size_t)b * Tn + t0 + band + g) * Hn + h) * Sn;
    float* prow0H = prow0G + (size_t)8 * Hn * Sn;
    float* prow1G = prow0G + (size_t)16 * Hn * Sn;
    float* prow1H = prow0G + (size_t)24 * Hn * Sn;

    // STG.128 column mapping after pair exchange: t -> 0,8,4,12
    const int colOff = 2 * t + ((t & 1) ? 6 : 0);
    const bool todd = (t & 1);

    for (int c = 0; c < NCH; c++) {
        cp_wait<0>();
        __syncthreads();
        const uint32_t kb_s = smb + (uint32_t)(c & 1) * 8192;
        const uint32_t vb_s = smb + SM_V + (uint32_t)(c & 1) * 8192;

        // prefetch next chunk into alt buffers
        if (c + 1 < NCH) {
            const unsigned char* src = kvb + (size_t)(c + 1) * CH_B;
            uint32_t dk = smb + (uint32_t)((c + 1) & 1) * 8192;
            uint32_t dv = smb + SM_V + (uint32_t)((c + 1) & 1) * 8192;
            #pragma unroll
            for (int u = 0; u < 4; u++)
                cpa16(dk + tid * 16 + u * 2048, src + OFF_K + tid * 16 + u * 2048);
            #pragma unroll
            for (int u = 0; u < 4; u++)
                cpa16(dv + tid * 16 + u * 2048, src + OFF_V + tid * 16 + u * 2048);
        }
        CP_COMMIT();

        #pragma unroll
        for (int jj = 0; jj < 4; jj++) {
            float S[2][2][4];
            #pragma unroll
            for (int m = 0; m < 2; m++)
                #pragma unroll
                for (int i = 0; i < 2; i++)
                    { S[m][i][0] = 0.f; S[m][i][1] = 0.f; S[m][i][2] = 0.f; S[m][i][3] = 0.f; }

            #pragma unroll
            for (int ks = 0; ks < 4; ks++) {
                uint32_t bh[4];
                ldsm_x4(bh, (kb_s + jj * 2048 + ks * 32 + lbase) ^ lxor);
                mma_f16(S[0][0], qf[0][ks], bh[0], bh[1]);
                mma_f16(S[0][1], qf[0][ks], bh[2], bh[3]);
                mma_f16(S[1][0], qf[1][ks], bh[0], bh[1]);
                mma_f16(S[1][1], qf[1][ks], bh[2], bh[3]);
            }

            const int col = c * 64 + jj * 16;
            uint32_t a[2][4];

            // --- per row-half: exp, normalize, pair-shuffled STG.128, pack A-frag ---
            {   // m0, G rows
                float x0 = ex2f(S[0][0][0]) * iG0, x1 = ex2f(S[0][0][1]) * iG0;
                float x2 = ex2f(S[0][1][0]) * iG0, x3 = ex2f(S[0][1][1]) * iG0;
                a[0][0] = packh2(x0, x1); a[0][2] = packh2(x2, x3);
                float s0 = todd ? x0 : x2, s1 = todd ? x1 : x3;
                float r0 = __shfl_xor_sync(0xffffffffu, s0, 1);
                float r1 = __shfl_xor_sync(0xffffffffu, s1, 1);
                float4 o = todd ? make_float4(r0, r1, x2, x3) : make_float4(x0, x1, r0, r1);
                __stcs((float4*)(prow0G + col + colOff), o);
            }
            {   // m0, H rows
                float x0 = ex2f(S[0][0][2]) * iH0, x1 = ex2f(S[0][0][3]) * iH0;
                float x2 = ex2f(S[0][1][2]) * iH0, x3 = ex2f(S[0][1][3]) * iH0;
                a[0][1] = packh2(x0, x1); a[0][3] = packh2(x2, x3);
                float s0 = todd ? x0 : x2, s1 = todd ? x1 : x3;
                float r0 = __shfl_xor_sync(0xffffffffu, s0, 1);
                float r1 = __shfl_xor_sync(0xffffffffu, s1, 1);
                float4 o = todd ? make_float4(r0, r1, x2, x3) : make_float4(x0, x1, r0, r1);
                __stcs((float4*)(prow0H + col + colOff), o);
            }
            {   // m1, G rows
                float x0 = ex2f(S[1][0][0]) * iG1, x1 = ex2f(S[1][0][1]) * iG1;
                float x2 = ex2f(S[1][1][0]) * iG1, x3 = ex2f(S[1][1][1]) * iG1;
                a[1][0] = packh2(x0, x1); a[1][2] = packh2(x2, x3);
                float s0 = todd ? x0 : x2, s1 = todd ? x1 : x3;
                float r0 = __shfl_xor_sync(0xffffffffu, s0, 1);
                float r1 = __shfl_xor_sync(0xffffffffu, s1, 1);
                float4 o = todd ? make_float4(r0, r1, x2, x3) : make_float4(x0, x1, r0, r1);
                __stcs((float4*)(prow1G + col + colOff), o);
            }
            {   // m1, H rows
                float x0 = ex2f(S[1][0][2]) * iH1, x1 = ex2f(S[1][0][3]) * iH1;
                float x2 = ex2f(S[1][1][2]) * iH1, x3 = ex2f(S[1][1][3]) * iH1;
                a[1][1] = packh2(x0, x1); a[1][3] = packh2(x2, x3);
                float s0 = todd ? x0 : x2, s1 = todd ? x1 : x3;
                float r0 = __shfl_xor_sync(0xffffffffu, s0, 1);
                float r1 = __shfl_xor_sync(0xffffffffu, s1, 1);
                float4 o = todd ? make_float4(r0, r1, x2, x3) : make_float4(x0, x1, r0, r1);
                __stcs((float4*)(prow1H + col + colOff), o);
            }

            #pragma unroll
            for (int p = 0; p < 4; p++) {
                uint32_t bv[4];
                ldsm_x4_t(bv, (vb_s + jj * 2048 + p * 32 + lbase) ^ lxor);
                mma_f16(O[0][2 * p],     a[0], bv[0], bv[2]);
                mma_f16(O[0][2 * p + 1], a[0], bv[1], bv[3]);
                mma_f16(O[1][2 * p],     a[1], bv[0], bv[2]);
                mma_f16(O[1][2 * p + 1], a[1], bv[1], bv[3]);
            }
        }
    }

    // ================= output (P pre-normalized; warp owns all keys) =================
    #pragma unroll
    for (int m = 0; m < 2; m++) {
        float* oarG = out_attn + (((size_t)b * Tn + t0 + band + m * 16 + g) * Hn + h) * Dn;
        float* oarH = oarG + 8 * RS;
        #pragma unroll
        for (int nd = 0; nd < 8; nd++) {
            *(float2*)(oarG + nd * 8 + 2 * t) = make_float2(O[m][nd][0], O[m][nd][1]);
            *(float2*)(oarH + nd * 8 + 2 * t) = make_float2(O[m][nd][2], O[m][nd][3]);
        }
    }
}

extern "C" void kernel_launch(void* const* d_in, const int* in_sizes, int n_in,
                              void* d_out, int out_size) {
    const float* q = (const float*)d_in[0];
    const float* k = (const float*)d_in[1];
    const float* v = (const float*)d_in[2];
    float* out_attn  = (float*)d_out;
    float* out_probs = (float*)d_out + (size_t)Bn * Tn * Hn * Dn;

    cudaFuncSetAttribute(attn_main,
                         cudaFuncAttributeMaxDynamicSharedMemorySize, SMEM_MAIN);

    dim3 pgrid(NCH, Hn, Bn);
    prep_kernel<<<pgrid, 128>>>(k, v);

    dim3 grid(Tn / MQc, Hn, Bn);   // 512 CTAs, 4 CTAs/SM -> single wave
    attn_main<<<grid, NT, SMEM_MAIN>>>(q, out_attn, out_probs);
}

// round 13
// speedup vs baseline: 1.3176x; 1.3176x over previous
#include <cuda_runtime.h>
#include <cuda_fp16.h>
#include <cstdint>

#define Bn 4
#define Tn 1024
#define Sn 1024
#define Hn 16
#define Dn 64
#define RS (Hn*Dn)
#define MQc 128              // queries per CTA
#define NKC 64               // keys per chunk
#define NCH (Sn/NKC)         // 16
#define NT 128

// per-(b,h,chunk) scratch: [K fp16 8KB][V fp16 8KB], swizzled smem-image layout,
// keys PERMUTED within each 16-group so C-fragment columns land contiguous.
#define CH_B 16384
#define OFF_K 0
#define OFF_V 8192
__device__ __align__(128) unsigned char g_kv[(size_t)Bn*Hn*NCH*CH_B];   // 16 MB

// smem: K double buffer 0/8K, V double buffer 16K/24K
#define SM_V 16384
#define SMEM_MAIN 32768

// exp(x) = ex2(x * log2e); fold log2e/8 into Q scale
#define QSCALE 0.18033688011112042f

// ---------------- PTX wrappers ----------------
__device__ __forceinline__ uint32_t smem_u32(const void* p) {
    uint32_t a;
    asm("{ .reg .u64 t; cvta.to.shared.u64 t, %1; cvt.u32.u64 %0, t; }" : "=r"(a) : "l"(p));
    return a;
}
__device__ __forceinline__ void ldsm_x4(uint32_t* r, uint32_t addr) {
    asm volatile("ldmatrix.sync.aligned.m8n8.x4.shared.b16 {%0,%1,%2,%3}, [%4];"
        : "=r"(r[0]), "=r"(r[1]), "=r"(r[2]), "=r"(r[3]) : "r"(addr));
}
__device__ __forceinline__ void ldsm_x4_t(uint32_t* r, uint32_t addr) {
    asm volatile("ldmatrix.sync.aligned.m8n8.x4.trans.shared.b16 {%0,%1,%2,%3}, [%4];"
        : "=r"(r[0]), "=r"(r[1]), "=r"(r[2]), "=r"(r[3]) : "r"(addr));
}
__device__ __forceinline__ void mma_f16(float* c, const uint32_t* a, uint32_t b0, uint32_t b1) {
    asm volatile("mma.sync.aligned.m16n8k16.row.col.f32.f16.f16.f32 "
        "{%0,%1,%2,%3}, {%4,%5,%6,%7}, {%8,%9}, {%0,%1,%2,%3};"
        : "+f"(c[0]), "+f"(c[1]), "+f"(c[2]), "+f"(c[3])
        : "r"(a[0]), "r"(a[1]), "r"(a[2]), "r"(a[3]), "r"(b0), "r"(b1));
}
__device__ __forceinline__ void cpa16(uint32_t s, const void* g) {
    asm volatile("cp.async.cg.shared.global [%0], [%1], 16;" :: "r"(s), "l"(g));
}
#define CP_COMMIT() asm volatile("cp.async.commit_group;" ::: "memory")
template<int N> __device__ __forceinline__ void cp_wait() {
    asm volatile("cp.async.wait_group %0;" :: "n"(N) : "memory");
}
__device__ __forceinline__ uint32_t packh2(float a, float b) {
    __half2 h = __floats2half2_rn(a, b);
    return *(uint32_t*)&h;
}
__device__ __forceinline__ float ex2f(float x) {
    float r;
    asm("ex2.approx.f32 %0, %1;" : "=f"(r) : "f"(x));
    return r;
}

// =================== prep: fp32 K/V -> fp16 swizzled, key-permuted tiles ===================
// logical key l within its 16-group -> physical position ((l>>1)&1)*8 + ((l&12)>>1) + (l&1)
__global__ __launch_bounds__(128)
void prep_kernel(const float* __restrict__ k, const float* __restrict__ v) {
    const int c = blockIdx.x, h = blockIdx.y, b = blockIdx.z, tid = threadIdx.x;
    const float* kb = k + (((size_t)b * Sn + c * NKC) * Hn + h) * Dn;
    const float* vb = v + (((size_t)b * Sn + c * NKC) * Hn + h) * Dn;
    unsigned char* dst = g_kv + (size_t)((b * Hn + h) * NCH + c) * CH_B;
    #pragma unroll
    for (int u = 0; u < 8; u++) {
        int fid = tid + u * 128;
        int r = fid >> 4, c4 = fid & 15;      // r = logical key row 0..63
        int l = r & 15;
        int pr = (r & ~15) | ((((l >> 1) & 1) << 3) | ((l & 12) >> 1) | (l & 1));
        uint32_t so = (uint32_t)(pr * 128 + c4 * 8) ^ ((uint32_t)(pr & 7) << 4);
        float4 x = *(const float4*)(kb + (size_t)r * RS + c4 * 4);
        *(uint2*)(dst + OFF_K + so) = make_uint2(packh2(x.x, x.y), packh2(x.z, x.w));
        float4 y = *(const float4*)(vb + (size_t)r * RS + c4 * 4);
        *(uint2*)(dst + OFF_V + so) = make_uint2(packh2(y.x, y.y), packh2(y.z, y.w));
    }
}

// =================== main attention kernel ===================
__global__ __launch_bounds__(NT, 4)
void attn_main(const float* __restrict__ q,
               float* __restrict__ out_attn, float* __restrict__ out_probs) {
    extern __shared__ char sm[];
    const uint32_t smb = smem_u32(sm);
    const int tid = threadIdx.x, lane = tid & 31, w = tid >> 5;
    const int band = w * 32;                  // warp owns 32 query rows
    const int t0 = blockIdx.x * MQc, h = blockIdx.y, b = blockIdx.z;
    const int g = lane >> 2, t = lane & 3;

    const unsigned char* kvb = g_kv + (size_t)((b * Hn + h) * NCH) * CH_B;
    const float* qbase = q + (((size_t)b * Tn + t0 + band + g) * Hn + h) * Dn;

    // ---- Q fp16 fragments, 2 m-tiles, scale (log2e/8) folded in ----
    uint32_t qf[2][4][4];
    #pragma unroll
    for (int m = 0; m < 2; m++) {
        const float* qrG = qbase + (size_t)(m * 16) * RS;
        const float* qrH = qrG + 8 * RS;
        #pragma unroll
        for (int ks = 0; ks < 4; ks++) {
            float2 f0 = *(const float2*)(qrG + ks * 16 + 2 * t);
            float2 f1 = *(const float2*)(qrH + ks * 16 + 2 * t);
            float2 f2 = *(const float2*)(qrG + ks * 16 + 2 * t + 8);
            float2 f3 = *(const float2*)(qrH + ks * 16 + 2 * t + 8);
            qf[m][ks][0] = packh2(f0.x * QSCALE, f0.y * QSCALE);
            qf[m][ks][1] = packh2(f1.x * QSCALE, f1.y * QSCALE);
            qf[m][ks][2] = packh2(f2.x * QSCALE, f2.y * QSCALE);
            qf[m][ks][3] = packh2(f3.x * QSCALE, f3.y * QSCALE);
        }
    }

    // ldmatrix lane addressing (within-tile SW128)
    const uint32_t rowoff = ((lane >> 4) & 1) * 8 + (lane & 7);
    const uint32_t colsel = ((lane >> 3) & 1) * 16;
    const uint32_t lbase = rowoff * 128 + colsel;
    const uint32_t lxor = (rowoff & 7) << 4;

    float sG[2] = {0.f, 0.f}, sH[2] = {0.f, 0.f};

    // ================= Pass A: rowsums (double-buffered 8KB K tiles, 16-key slabs) =================
    {
        #pragma unroll
        for (int u = 0; u < 4; u++)
            cpa16(smb + tid * 16 + u * 2048, kvb + OFF_K + tid * 16 + u * 2048);
        CP_COMMIT();
        #pragma unroll
        for (int u = 0; u < 4; u++)
            cpa16(smb + 8192 + tid * 16 + u * 2048, kvb + CH_B + OFF_K + tid * 16 + u * 2048);
        CP_COMMIT();

        for (int c = 0; c < NCH; c++) {
            cp_wait<1>();
            __syncthreads();
            const uint32_t kb_s = smb + (uint32_t)(c & 1) * 8192;

            #pragma unroll
            for (int jj = 0; jj < 4; jj++) {
                float S[2][2][4];
                #pragma unroll
                for (int m = 0; m < 2; m++)
                    #pragma unroll
                    for (int i = 0; i < 2; i++)
                        { S[m][i][0] = 0.f; S[m][i][1] = 0.f; S[m][i][2] = 0.f; S[m][i][3] = 0.f; }
                #pragma unroll
                for (int ks = 0; ks < 4; ks++) {
                    uint32_t bh[4];
                    ldsm_x4(bh, (kb_s + jj * 2048 + ks * 32 + lbase) ^ lxor);
                    mma_f16(S[0][0], qf[0][ks], bh[0], bh[1]);
                    mma_f16(S[0][1], qf[0][ks], bh[2], bh[3]);
                    mma_f16(S[1][0], qf[1][ks], bh[0], bh[1]);
                    mma_f16(S[1][1], qf[1][ks], bh[2], bh[3]);
                }
                #pragma unroll
                for (int m = 0; m < 2; m++)
                    #pragma unroll
                    for (int i = 0; i < 2; i++) {
                        sG[m] += ex2f(S[m][i][0]) + ex2f(S[m][i][1]);
                        sH[m] += ex2f(S[m][i][2]) + ex2f(S[m][i][3]);
                    }
            }
            __syncthreads();
            if (c + 2 < NCH) {
                const unsigned char* src = kvb + (size_t)(c + 2) * CH_B + OFF_K;
                uint32_t d = smb + (uint32_t)(c & 1) * 8192;
                #pragma unroll
                for (int u = 0; u < 4; u++)
                    cpa16(d + tid * 16 + u * 2048, src + tid * 16 + u * 2048);
            }
            CP_COMMIT();
        }
        cp_wait<0>();
        __syncthreads();
    }
    #pragma unroll
    for (int m = 0; m < 2; m++) {
        sG[m] += __shfl_xor_sync(0xffffffffu, sG[m], 1);
        sG[m] += __shfl_xor_sync(0xffffffffu, sG[m], 2);
        sH[m] += __shfl_xor_sync(0xffffffffu, sH[m], 1);
        sH[m] += __shfl_xor_sync(0xffffffffu, sH[m], 2);
    }
    const float iG0 = 1.f / sG[0], iH0 = 1.f / sH[0];
    const float iG1 = 1.f / sG[1], iH1 = 1.f / sH[1];

    // pass B prologue: K0 + V0 in one group
    #pragma unroll
    for (int u = 0; u < 4; u++)
        cpa16(smb + tid * 16 + u * 2048, kvb + OFF_K + tid * 16 + u * 2048);
    #pragma unroll
    for (int u = 0; u < 4; u++)
        cpa16(smb + SM_V + tid * 16 + u * 2048, kvb + OFF_V + tid * 16 + u * 2048);
    CP_COMMIT();

    // ================= Pass B: probs + PV (16-key groups, normalized P) =================
    float O[2][8][4];
    #pragma unroll
    for (int m = 0; m < 2; m++)
        #pragma unroll
        for (int i = 0; i < 8; i++)
            { O[m][i][0] = 0.f; O[m][i][1] = 0.f; O[m][i][2] = 0.f; O[m][i][3] = 0.f; }

    float* prow0G = out_probs + (((size_t)b * Tn + t0 + band + g) * Hn + h) * Sn;
    float* prow0H = prow0G + (size_t)8 * Hn * Sn;
    float* prow1G = prow0G + (size_t)16 * Hn * Sn;
    float* prow1H = prow0G + (size_t)24 * Hn * Sn;

    for (int c = 0; c < NCH; c++) {
        cp_wait<0>();
        __syncthreads();
        const uint32_t kb_s = smb + (uint32_t)(c & 1) * 8192;
        const uint32_t vb_s = smb + SM_V + (uint32_t)(c & 1) * 8192;

        // prefetch next chunk into alt buffers
        if (c + 1 < NCH) {
            const unsigned char* src = kvb + (size_t)(c + 1) * CH_B;
            uint32_t dk = smb + (uint32_t)((c + 1) & 1) * 8192;
            uint32_t dv = smb + SM_V + (uint32_t)((c + 1) & 1) * 8192;
            #pragma unroll
            for (int u = 0; u < 4; u++)
                cpa16(dk + tid * 16 + u * 2048, src + OFF_K + tid * 16 + u * 2048);
            #pragma unroll
            for (int u = 0; u < 4; u++)
                cpa16(dv + tid * 16 + u * 2048, src + OFF_V + tid * 16 + u * 2048);
        }
        CP_COMMIT();

        #pragma unroll
        for (int jj = 0; jj < 4; jj++) {
            float S[2][2][4];
            #pragma unroll
            for (int m = 0; m < 2; m++)
                #pragma unroll
                for (int i = 0; i < 2; i++)
                    { S[m][i][0] = 0.f; S[m][i][1] = 0.f; S[m][i][2] = 0.f; S[m][i][3] = 0.f; }

            #pragma unroll
            for (int ks = 0; ks < 4; ks++) {
                uint32_t bh[4];
                ldsm_x4(bh, (kb_s + jj * 2048 + ks * 32 + lbase) ^ lxor);
                mma_f16(S[0][0], qf[0][ks], bh[0], bh[1]);
                mma_f16(S[0][1], qf[0][ks], bh[2], bh[3]);
                mma_f16(S[1][0], qf[1][ks], bh[0], bh[1]);
                mma_f16(S[1][1], qf[1][ks], bh[2], bh[3]);
            }

            // logical columns: physical {2t,2t+1} -> 4t,4t+1 ; {8+2t,9+2t} -> 4t+2,4t+3
            const int col = c * 64 + jj * 16 + 4 * t;
            uint32_t a[2][4];
            {   // m-tile 0
                float g0 = ex2f(S[0][0][0]) * iG0, g1 = ex2f(S[0][0][1]) * iG0;
                float h0 = ex2f(S[0][0][2]) * iH0, h1 = ex2f(S[0][0][3]) * iH0;
                float g2 = ex2f(S[0][1][0]) * iG0, g3 = ex2f(S[0][1][1]) * iG0;
                float h2 = ex2f(S[0][1][2]) * iH0, h3 = ex2f(S[0][1][3]) * iH0;
                __stcs((float4*)(prow0G + col), make_float4(g0, g1, g2, g3));
                __stcs((float4*)(prow0H + col), make_float4(h0, h1, h2, h3));
                a[0][0] = packh2(g0, g1); a[0][1] = packh2(h0, h1);
                a[0][2] = packh2(g2, g3); a[0][3] = packh2(h2, h3);
            }
            {   // m-tile 1
                float g0 = ex2f(S[1][0][0]) * iG1, g1 = ex2f(S[1][0][1]) * iG1;
                float h0 = ex2f(S[1][0][2]) * iH1, h1 = ex2f(S[1][0][3]) * iH1;
                float g2 = ex2f(S[1][1][0]) * iG1, g3 = ex2f(S[1][1][1]) * iG1;
                float h2 = ex2f(S[1][1][2]) * iH1, h3 = ex2f(S[1][1][3]) * iH1;
                __stcs((float4*)(prow1G + col), make_float4(g0, g1, g2, g3));
                __stcs((float4*)(prow1H + col), make_float4(h0, h1, h2, h3));
                a[1][0] = packh2(g0, g1); a[1][1] = packh2(h0, h1);
                a[1][2] = packh2(g2, g3); a[1][3] = packh2(h2, h3);
            }

            #pragma unroll
            for (int p = 0; p < 4; p++) {
                uint32_t bv[4];
                ldsm_x4_t(bv, (vb_s + jj * 2048 + p * 32 + lbase) ^ lxor);
                mma_f16(O[0][2 * p],     a[0], bv[0], bv[2]);
                mma_f16(O[0][2 * p + 1], a[0], bv[1], bv[3]);
                mma_f16(O[1][2 * p],     a[1], bv[0], bv[2]);
                mma_f16(O[1][2 * p + 1], a[1], bv[1], bv[3]);
            }
        }
    }

    // ================= output (P pre-normalized; warp owns all keys) =================
    #pragma unroll
    for (int m = 0; m < 2; m++) {
        float* oarG = out_attn + (((size_t)b * Tn + t0 + band + m * 16 + g) * Hn + h) * Dn;
        float* oarH = oarG + 8 * RS;
        #pragma unroll
        for (int nd = 0; nd < 8; nd++) {
            *(float2*)(oarG + nd * 8 + 2 * t) = make_float2(O[m][nd][0], O[m][nd][1]);
            *(float2*)(oarH + nd * 8 + 2 * t) = make_float2(O[m][nd][2], O[m][nd][3]);
        }
    }
}

extern "C" void kernel_launch(void* const* d_in, const int* in_sizes, int n_in,
                              void* d_out, int out_size) {
    const float* q = (const float*)d_in[0];
    const float* k = (const float*)d_in[1];
    const float* v = (const float*)d_in[2];
    float* out_attn  = (float*)d_out;
    float* out_probs = (float*)d_out + (size_t)Bn * Tn * Hn * Dn;

    cudaFuncSetAttribute(attn_main,
                         cudaFuncAttributeMaxDynamicSharedMemorySize, SMEM_MAIN);

    dim3 pgrid(NCH, Hn, Bn);
    prep_kernel<<<pgrid, 128>>>(k, v);

    dim3 grid(Tn / MQc, Hn, Bn);   // 512 CTAs, 4 CTAs/SM -> single wave
    attn_main<<<grid, NT, SMEM_MAIN>>>(q, out_attn, out_probs);
}